// round 1
// baseline (speedup 1.0000x reference)
#include <cuda_runtime.h>
#include <math.h>

#define BB 8
#define TT 2048
#define EE 1024
#define HH 128
#define BT (BB*TT)

// ---------------- scratch (device globals: allocation-free) ----------------
__device__ float g_k[BT*HH];
__device__ float g_q[BT*HH];
__device__ float g_v[BT*HH];
__device__ float g_S[(size_t)BB*TT*TT];          // 134 MB score scratch (zero-init)
__device__ float g_pmax[8*BT];
__device__ float g_psum[8*BT];
__device__ float g_cmax[BT];
__device__ float g_crcp[BT];

// ---------------- K1: q/k/v = x @ W  (M=BT, K=E, N=H) ----------------------
// block = 256 threads, tile 64(M) x 128(N), BK=16; micro 8x4 per thread
__global__ void qkv_kernel(const float* __restrict__ x,
                           const float* __restrict__ Wk,
                           const float* __restrict__ Wq,
                           const float* __restrict__ Wv) {
    const float* W   = (blockIdx.y == 0) ? Wk : (blockIdx.y == 1) ? Wq : Wv;
    float*       out = (blockIdx.y == 0) ? g_k : (blockIdx.y == 1) ? g_q : g_v;

    __shared__ float xs[64][17];
    __shared__ float ws[16][128];

    int tid = threadIdx.x;
    int tx = tid & 31;      // 32 groups of 4 cols -> 128
    int ty = tid >> 5;      // 8 groups of 8 rows  -> 64
    int m0 = blockIdx.x * 64;

    float acc[8][4];
#pragma unroll
    for (int i = 0; i < 8; i++)
#pragma unroll
        for (int j = 0; j < 4; j++) acc[i][j] = 0.f;

    for (int k0 = 0; k0 < EE; k0 += 16) {
        {   // x tile: 64x16 = 256 float4, one per thread
            int r = tid >> 2, c4 = tid & 3;
            float4 v = *(const float4*)&x[(size_t)(m0 + r) * EE + k0 + c4 * 4];
            xs[r][c4*4+0] = v.x; xs[r][c4*4+1] = v.y;
            xs[r][c4*4+2] = v.z; xs[r][c4*4+3] = v.w;
        }
#pragma unroll
        for (int i = 0; i < 2; i++) {  // W tile: 16x128 = 512 float4, two per thread
            int idx = tid * 2 + i;
            int r = idx >> 5, c4 = idx & 31;
            *(float4*)&ws[r][c4 * 4] = *(const float4*)&W[(size_t)(k0 + r) * HH + c4 * 4];
        }
        __syncthreads();
#pragma unroll
        for (int kk = 0; kk < 16; kk++) {
            float a[8], bv[4];
#pragma unroll
            for (int i = 0; i < 8; i++) a[i] = xs[ty * 8 + i][kk];
#pragma unroll
            for (int j = 0; j < 4; j++) bv[j] = ws[kk][tx * 4 + j];
#pragma unroll
            for (int i = 0; i < 8; i++)
#pragma unroll
                for (int j = 0; j < 4; j++) acc[i][j] += a[i] * bv[j];
        }
        __syncthreads();
    }
#pragma unroll
    for (int i = 0; i < 8; i++) {
        int row = m0 + ty * 8 + i;
        float4 v = make_float4(acc[i][0], acc[i][1], acc[i][2], acc[i][3]);
        *(float4*)&out[(size_t)row * HH + tx * 4] = v;
    }
}

// ---------------- K2: S[b,t,s] = sqrt(H) * q[b,t] . k[b,s] -----------------
// block = 256, tile 128(t) x 64(s), K=H in chunks of 16; micro 8x4
__global__ void score_kernel() {
    int t0 = blockIdx.x * 128;
    int s0 = blockIdx.y * 64;
    int b  = blockIdx.z;
    if (t0 + 127 < s0) return;             // tile fully above diagonal

    __shared__ float qs[128][17];
    __shared__ float ks[64][17];

    const float* qb = g_q + (size_t)b * TT * HH;
    const float* kb = g_k + (size_t)b * TT * HH;

    int tid = threadIdx.x;
    int tx = tid & 15;      // 16 groups * 4 cols = 64 (s)
    int ty = tid >> 4;      // 16 groups * 8 rows = 128 (t)

    float acc[8][4];
#pragma unroll
    for (int i = 0; i < 8; i++)
#pragma unroll
        for (int j = 0; j < 4; j++) acc[i][j] = 0.f;

    for (int h0 = 0; h0 < HH; h0 += 16) {
#pragma unroll
        for (int i = 0; i < 2; i++) {   // q tile: 128x16 = 512 float4
            int idx = tid * 2 + i;
            int r = idx >> 2, c4 = idx & 3;
            float4 v = *(const float4*)&qb[(size_t)(t0 + r) * HH + h0 + c4 * 4];
            qs[r][c4*4+0] = v.x; qs[r][c4*4+1] = v.y;
            qs[r][c4*4+2] = v.z; qs[r][c4*4+3] = v.w;
        }
        {   // k tile: 64x16 = 256 float4
            int r = tid >> 2, c4 = tid & 3;
            float4 v = *(const float4*)&kb[(size_t)(s0 + r) * HH + h0 + c4 * 4];
            ks[r][c4*4+0] = v.x; ks[r][c4*4+1] = v.y;
            ks[r][c4*4+2] = v.z; ks[r][c4*4+3] = v.w;
        }
        __syncthreads();
#pragma unroll
        for (int kk = 0; kk < 16; kk++) {
            float a[8], bv[4];
#pragma unroll
            for (int i = 0; i < 8; i++) a[i] = qs[ty * 8 + i][kk];
#pragma unroll
            for (int j = 0; j < 4; j++) bv[j] = ks[tx * 4 + j][kk];
#pragma unroll
            for (int i = 0; i < 8; i++)
#pragma unroll
                for (int j = 0; j < 4; j++) acc[i][j] += a[i] * bv[j];
        }
        __syncthreads();
    }

    float* Sb = g_S + (size_t)b * TT * TT;
    const float scale = 11.31370849898476f;   // sqrt(128)
#pragma unroll
    for (int i = 0; i < 8; i++) {
        int t = t0 + ty * 8 + i;
        float4 v = make_float4(acc[i][0]*scale, acc[i][1]*scale,
                               acc[i][2]*scale, acc[i][3]*scale);
        *(float4*)&Sb[(size_t)t * TT + s0 + tx * 4] = v;
    }
}

// -------- K3a: per-column online max/sum over a T/8 chunk of t -------------
__global__ void colred_partial() {
    int col = blockIdx.x * 256 + threadIdx.x;   // [0, BT)
    int b = col / TT;
    int s = col % TT;
    int c = blockIdx.y;
    int t0 = c * (TT / 8);
    int t1 = t0 + (TT / 8);
    const float* Sb = g_S + (size_t)b * TT * TT;

    float m = -INFINITY, d = 0.f;
    int tstart = (s > t0) ? s : t0;
    for (int t = tstart; t < t1; t++) {
        float v = Sb[(size_t)t * TT + s];
        float nm = fmaxf(m, v);
        d = d * __expf(m - nm) + __expf(v - nm);
        m = nm;
    }
    g_pmax[c * BT + col] = m;
    g_psum[c * BT + col] = d;
}

// -------- K3b: combine 8 partials per column; store max and 1/den ----------
__global__ void colred_combine() {
    int col = blockIdx.x * 256 + threadIdx.x;
    float m = -INFINITY;
#pragma unroll
    for (int c = 0; c < 8; c++) m = fmaxf(m, g_pmax[c * BT + col]);
    float d = 0.f;
#pragma unroll
    for (int c = 0; c < 8; c++) {
        float pm = g_pmax[c * BT + col];
        float ps = g_psum[c * BT + col];
        d += ps * __expf(pm - m);      // pm=-inf,ps=0 -> 0 contribution
    }
    g_cmax[col] = m;
    g_crcp[col] = 1.f / d;
}

// ---------------- K4: out[b,t,:] = sum_s P[t,s] * v[b,s,:] -----------------
// P[t,s] = exp(S[t,s]-cmax[s]) * crcp[s] for s<=t else 0
// block = 256, tile 64(t) x 128(H), s chunks of 16; micro 8x4
__global__ void out_kernel(float* __restrict__ out) {
    int t0 = blockIdx.x * 64;
    int b  = blockIdx.y;

    __shared__ float wsm[64][17];
    __shared__ float vs[16][128];

    const float* Sb = g_S + (size_t)b * TT * TT;
    const float* vb = g_v + (size_t)b * TT * HH;
    const float* cmax = g_cmax + b * TT;
    const float* crcp = g_crcp + b * TT;

    int tid = threadIdx.x;
    int tx = tid & 31;      // 32 groups * 4 cols = 128 (H)
    int ty = tid >> 5;      // 8 groups * 8 rows = 64 (t)

    float acc[8][4];
#pragma unroll
    for (int i = 0; i < 8; i++)
#pragma unroll
        for (int j = 0; j < 4; j++) acc[i][j] = 0.f;

    int nch = (t0 + 63) / 16 + 1;           // s chunks needed (s <= t_max)
    for (int ch = 0; ch < nch; ch++) {
        int s0 = ch * 16;
#pragma unroll
        for (int i = 0; i < 4; i++) {       // weight tile 64x16, 4 entries/thread
            int idx = i * 256 + tid;
            int r = idx >> 4, c = idx & 15;
            int t = t0 + r, s = s0 + c;
            float val = 0.f;
            if (s <= t) {
                float sc = Sb[(size_t)t * TT + s];
                val = __expf(sc - cmax[s]) * crcp[s];
            }
            wsm[r][c] = val;
        }
#pragma unroll
        for (int i = 0; i < 2; i++) {       // v tile 16x128 = 512 float4
            int idx = tid * 2 + i;
            int r = idx >> 5, c4 = idx & 31;
            *(float4*)&vs[r][c4 * 4] = *(const float4*)&vb[(size_t)(s0 + r) * HH + c4 * 4];
        }
        __syncthreads();
#pragma unroll
        for (int kk = 0; kk < 16; kk++) {
            float a[8], bv[4];
#pragma unroll
            for (int i = 0; i < 8; i++) a[i] = wsm[ty * 8 + i][kk];
#pragma unroll
            for (int j = 0; j < 4; j++) bv[j] = vs[kk][tx * 4 + j];
#pragma unroll
            for (int i = 0; i < 8; i++)
#pragma unroll
                for (int j = 0; j < 4; j++) acc[i][j] += a[i] * bv[j];
        }
        __syncthreads();
    }
#pragma unroll
    for (int i = 0; i < 8; i++) {
        int t = t0 + ty * 8 + i;
        float4 v = make_float4(acc[i][0], acc[i][1], acc[i][2], acc[i][3]);
        *(float4*)&out[((size_t)b * TT + t) * HH + tx * 4] = v;
    }
}

// ---------------------------------------------------------------------------
extern "C" void kernel_launch(void* const* d_in, const int* in_sizes, int n_in,
                              void* d_out, int out_size) {
    const float* x  = (const float*)d_in[0];
    const float* Wk = (const float*)d_in[1];
    const float* Wq = (const float*)d_in[2];
    const float* Wv = (const float*)d_in[3];
    float* out = (float*)d_out;

    qkv_kernel<<<dim3(BT / 64, 3), 256>>>(x, Wk, Wq, Wv);
    score_kernel<<<dim3(TT / 128, TT / 64, BB), 256>>>();
    colred_partial<<<dim3(BT / 256, 8), 256>>>();
    colred_combine<<<BT / 256, 256>>>();
    out_kernel<<<dim3(TT / 64, BB), 256>>>(out);
}